// round 17
// baseline (speedup 1.0000x reference)
#include <cuda_runtime.h>
#include <cuda_fp16.h>
#include <cstdint>

#define T_TOKENS 8192
#define D_DIM    1024
#define E_EXP    8
#define O_DIM    1024
#define CAP      8192
#define ROWS_CAP (E_EXP * CAP)

// ---------------- device scratch (no allocations allowed) ----------------
__device__ int   g_cnt[E_EXP];
__device__ int   g_exp [2 * T_TOKENS];
__device__ int   g_rank[2 * T_TOKENS];
__device__ float g_w   [2 * T_TOKENS];
__device__ int   g_rows[ROWS_CAP];                       // segment slot -> token (valid slots only)
__device__ __half g_xh[(size_t)(T_TOKENS + 8) * D_DIM];  // fp16 tokens + zero rows (never written)
__device__ __half g_we[(size_t)E_EXP * O_DIM * D_DIM];
__device__ float  g_ys[(size_t)ROWS_CAP * O_DIM];

// ---------------- helpers ----------------
__device__ __forceinline__ uint32_t smem_u32(const void* p) {
    return (uint32_t)__cvta_generic_to_shared(p);
}
__device__ __forceinline__ void cp16(uint32_t s, const void* g) {
    asm volatile("cp.async.cg.shared.global [%0], [%1], 16;" :: "r"(s), "l"(g) : "memory");
}
__device__ __forceinline__ void cp_commit() {
    asm volatile("cp.async.commit_group;" ::: "memory");
}
#define LDSM4(r0, r1, r2, r3, addr) \
    asm volatile("ldmatrix.sync.aligned.m8n8.x4.shared.b16 {%0,%1,%2,%3}, [%4];" \
                 : "=r"(r0), "=r"(r1), "=r"(r2), "=r"(r3) : "r"(addr))

// ---------------- phase kernels ----------------
// We fp32 -> fp16 (8 floats / thread). Runs on a forked stream.
__global__ void convert_we_kernel(const float* __restrict__ We) {
    size_t i = ((size_t)blockIdx.x * blockDim.x + threadIdx.x) * 8;
    float4 a = *(const float4*)(We + i);
    float4 b = *(const float4*)(We + i + 4);
    __half h[8];
    h[0] = __float2half_rn(a.x); h[1] = __float2half_rn(a.y);
    h[2] = __float2half_rn(a.z); h[3] = __float2half_rn(a.w);
    h[4] = __float2half_rn(b.x); h[5] = __float2half_rn(b.y);
    h[6] = __float2half_rn(b.z); h[7] = __float2half_rn(b.w);
    *(uint4*)(g_we + i) = *(const uint4*)h;
}

// x fp32 -> fp16 in token order; block 0 zeroes routing counters (gate runs
// after this kernel on the same stream).
__global__ void convert_x_kernel(const float* __restrict__ x) {
    if (blockIdx.x == 0 && threadIdx.x < E_EXP) g_cnt[threadIdx.x] = 0;
    size_t i = ((size_t)blockIdx.x * blockDim.x + threadIdx.x) * 8;
    float4 a = *(const float4*)(x + i);
    float4 b = *(const float4*)(x + i + 4);
    __half h[8];
    h[0] = __float2half_rn(a.x); h[1] = __float2half_rn(a.y);
    h[2] = __float2half_rn(a.z); h[3] = __float2half_rn(a.w);
    h[4] = __float2half_rn(b.x); h[5] = __float2half_rn(b.y);
    h[6] = __float2half_rn(b.z); h[7] = __float2half_rn(b.w);
    *(uint4*)(g_xh + i) = *(const uint4*)h;
}

// Gate: 32 tokens/block, Wg staged in smem, one warp -> 4 tokens.
// Records per-choice (expert, rank, weight) and segment-slot -> token index.
__global__ __launch_bounds__(256) void gate_kernel(const float* __restrict__ x,
                                                   const float* __restrict__ Wg) {
    __shared__ float wgs[E_EXP * D_DIM];
    int tid = threadIdx.x;
    for (int i = tid; i < E_EXP * D_DIM; i += 256) wgs[i] = Wg[i];
    __syncthreads();

    int warp = tid >> 5, lane = tid & 31;
    #pragma unroll
    for (int q = 0; q < 4; q++) {
        int t = blockIdx.x * 32 + warp * 4 + q;
        const float* xr = x + (size_t)t * D_DIM;
        float acc[E_EXP];
        #pragma unroll
        for (int e = 0; e < E_EXP; e++) acc[e] = 0.f;
        for (int k = 0; k < D_DIM / 32; k++) {
            float xv = xr[k * 32 + lane];
            #pragma unroll
            for (int e = 0; e < E_EXP; e++)
                acc[e] += xv * wgs[e * D_DIM + k * 32 + lane];
        }
        #pragma unroll
        for (int e = 0; e < E_EXP; e++)
            #pragma unroll
            for (int o = 16; o > 0; o >>= 1)
                acc[e] += __shfl_xor_sync(0xffffffffu, acc[e], o);

        if (lane == 0) {
            int i0 = 0; float v0 = acc[0];
            #pragma unroll
            for (int e = 1; e < E_EXP; e++)
                if (acc[e] > v0) { v0 = acc[e]; i0 = e; }
            int i1 = -1; float v1 = -3.4e38f;
            #pragma unroll
            for (int e = 0; e < E_EXP; e++) {
                if (e == i0) continue;
                if (acc[e] > v1) { v1 = acc[e]; i1 = e; }
            }
            float ex = __expf(v1 - v0);
            float inv = 1.f / (1.f + ex);
            int p0 = atomicAdd(&g_cnt[i0], 1);
            int p1 = atomicAdd(&g_cnt[i1], 1);
            g_exp[2 * t] = i0;     g_rank[2 * t] = p0;     g_w[2 * t] = inv;
            g_exp[2 * t + 1] = i1; g_rank[2 * t + 1] = p1; g_w[2 * t + 1] = ex * inv;
            g_rows[i0 * CAP + p0] = t;
            g_rows[i1 * CAP + p1] = t;
        }
    }
}

// ---------------- fp16 HMMA segmented GEMM (gathered A, ldmatrix frags) ----
// CTA tile 128x128, BK=32, 3-stage cp.async, 8 warps (4x2), warp tile 32x64.
// Pad rows (slot >= cnt) are mapped to the zero row in-kernel; no pad pass.
#define BK       32
#define RSTRIDE  40                         // halves per smem row (80B pad)
#define NCHUNK   (D_DIM / BK)               // 32
#define TILE_H   (128 * RSTRIDE)
#define STAGE_B  (2 * TILE_H * 2)           // A tile + B tile, bytes
#define GEMM_SMEM (3 * STAGE_B)             // 61440

__global__ __launch_bounds__(256, 2) void expert_gemm_hmma() {
    int e   = blockIdx.y >> 6;
    int lr0 = (blockIdx.y & 63) * 128;
    int cnt = g_cnt[e];
    if (lr0 >= cnt) return;
    int r0 = e * CAP + lr0;
    int o0 = blockIdx.x * 128;

    __shared__ int stok[128];
    extern __shared__ __half sm[];
    uint32_t sbase = smem_u32(sm);

    int tid = threadIdx.x;
    int lane = tid & 31, warp = tid >> 5;
    int wm = warp & 3, wn = warp >> 2;

    if (tid < 128)
        stok[tid] = (lr0 + tid < cnt) ? g_rows[r0 + tid] : T_TOKENS;  // pad -> zero row
    __syncthreads();

    // loader assignment: row = tid>>2, 16B seg = tid&3
    int lrow0 = tid >> 2, lseg = tid & 3;
    const __half* pA[2];
    const __half* pB[2];
    #pragma unroll
    for (int i = 0; i < 2; i++) {
        int row = lrow0 + 64 * i;
        pA[i] = g_xh + (size_t)stok[row] * D_DIM + lseg * 8;
        pB[i] = g_we + ((size_t)e * O_DIM + o0 + row) * D_DIM + lseg * 8;
    }
    uint32_t so[2];
    #pragma unroll
    for (int i = 0; i < 2; i++)
        so[i] = (uint32_t)((lrow0 + 64 * i) * (RSTRIDE * 2) + lseg * 16);

    auto load_chunk = [&](int c, int s) {
        uint32_t sA = sbase + (uint32_t)s * STAGE_B;
        uint32_t sB = sA + TILE_H * 2;
        #pragma unroll
        for (int i = 0; i < 2; i++) {
            cp16(sA + so[i], pA[i] + c * BK);
            cp16(sB + so[i], pB[i] + c * BK);
        }
        cp_commit();
    };

    // ldmatrix per-lane fragment offsets (bytes within a tile)
    uint32_t aoff = ((uint32_t)(32 * wm + (lane & 15)) * RSTRIDE + (lane >> 4) * 8) * 2;
    uint32_t boff = ((uint32_t)(64 * wn + (lane & 7) + 8 * (lane >> 4)) * RSTRIDE
                     + ((lane >> 3) & 1) * 8) * 2;

    float acc[2][8][4];
    #pragma unroll
    for (int i = 0; i < 2; i++)
        #pragma unroll
        for (int j = 0; j < 8; j++)
            #pragma unroll
            for (int q = 0; q < 4; q++) acc[i][j][q] = 0.f;

    load_chunk(0, 0);
    load_chunk(1, 1);

    for (int c = 0; c < NCHUNK; c++) {
        int s = c % 3;
        if (c < NCHUNK - 1)
            asm volatile("cp.async.wait_group 1;" ::: "memory");
        else
            asm volatile("cp.async.wait_group 0;" ::: "memory");
        __syncthreads();
        if (c + 2 < NCHUNK) load_chunk(c + 2, (c + 2) % 3);

        uint32_t As_b = sbase + (uint32_t)s * STAGE_B;
        uint32_t Bs_b = As_b + TILE_H * 2;
        #pragma unroll
        for (int kk = 0; kk < 2; kk++) {
            uint32_t kbb = (uint32_t)(kk * 16) * 2;
            uint32_t a[2][4], b[8][2];
            #pragma unroll
            for (int i = 0; i < 2; i++)
                LDSM4(a[i][0], a[i][1], a[i][2], a[i][3],
                      As_b + aoff + (uint32_t)i * (16 * RSTRIDE * 2) + kbb);
            #pragma unroll
            for (int jp = 0; jp < 4; jp++)
                LDSM4(b[2 * jp][0], b[2 * jp][1], b[2 * jp + 1][0], b[2 * jp + 1][1],
                      Bs_b + boff + (uint32_t)jp * (16 * RSTRIDE * 2) + kbb);
            #pragma unroll
            for (int i = 0; i < 2; i++)
                #pragma unroll
                for (int j = 0; j < 8; j++)
                    asm volatile(
                        "mma.sync.aligned.m16n8k16.row.col.f32.f16.f16.f32 "
                        "{%0,%1,%2,%3}, {%4,%5,%6,%7}, {%8,%9}, {%0,%1,%2,%3};"
                        : "+f"(acc[i][j][0]), "+f"(acc[i][j][1]),
                          "+f"(acc[i][j][2]), "+f"(acc[i][j][3])
                        : "r"(a[i][0]), "r"(a[i][1]), "r"(a[i][2]), "r"(a[i][3]),
                          "r"(b[j][0]), "r"(b[j][1]));
        }
    }

    int g = lane >> 2, tig = lane & 3;
    #pragma unroll
    for (int i = 0; i < 2; i++) {
        int rbase = r0 + 32 * wm + 16 * i + g;
        #pragma unroll
        for (int j = 0; j < 8; j++) {
            int col = o0 + 64 * wn + 8 * j + 2 * tig;
            float2 v0 = make_float2(acc[i][j][0], acc[i][j][1]);
            float2 v1 = make_float2(acc[i][j][2], acc[i][j][3]);
            *(float2*)(g_ys + (size_t)rbase * O_DIM + col) = v0;
            *(float2*)(g_ys + (size_t)(rbase + 8) * O_DIM + col) = v1;
        }
    }
}

// out[t,:] = w0*(ys[s0,:] + be[e0,:]) + w1*(ys[s1,:] + be[e1,:])
__global__ __launch_bounds__(256) void combine_kernel(const float* __restrict__ be,
                                                      float* __restrict__ out) {
    int t = blockIdx.x;
    int e0 = g_exp[2 * t], e1 = g_exp[2 * t + 1];
    float w0 = g_w[2 * t], w1 = g_w[2 * t + 1];
    size_t s0 = (size_t)e0 * CAP + g_rank[2 * t];
    size_t s1 = (size_t)e1 * CAP + g_rank[2 * t + 1];
    int o = threadIdx.x * 4;
    float4 y0 = *(const float4*)(g_ys + s0 * O_DIM + o);
    float4 y1 = *(const float4*)(g_ys + s1 * O_DIM + o);
    float4 b0 = *(const float4*)(be + (size_t)e0 * O_DIM + o);
    float4 b1 = *(const float4*)(be + (size_t)e1 * O_DIM + o);
    float4 r;
    r.x = w0 * (y0.x + b0.x) + w1 * (y1.x + b1.x);
    r.y = w0 * (y0.y + b0.y) + w1 * (y1.y + b1.y);
    r.z = w0 * (y0.z + b0.z) + w1 * (y1.z + b1.z);
    r.w = w0 * (y0.w + b0.w) + w1 * (y1.w + b1.w);
    *(float4*)(out + (size_t)t * O_DIM + o) = r;
}

extern "C" void kernel_launch(void* const* d_in, const int* in_sizes, int n_in,
                              void* d_out, int out_size) {
    const float* x  = (const float*)d_in[0];   // [4,2048,1024]
    const float* Wg = (const float*)d_in[1];   // [8,1024]
    const float* We = (const float*)d_in[2];   // [8,1024,1024]
    const float* be = (const float*)d_in[3];   // [8,1024]
    float* out = (float*)d_out;                // [4,2048,1024]

    static cudaStream_t s_we = nullptr;
    static cudaEvent_t  ev_fork = nullptr, ev_join = nullptr;
    static int init_done = 0;
    if (!init_done) {
        cudaFuncSetAttribute(expert_gemm_hmma,
                             cudaFuncAttributeMaxDynamicSharedMemorySize, GEMM_SMEM);
        cudaStreamCreateWithFlags(&s_we, cudaStreamNonBlocking);
        cudaEventCreateWithFlags(&ev_fork, cudaEventDisableTiming);
        cudaEventCreateWithFlags(&ev_join, cudaEventDisableTiming);
        init_done = 1;
    }

    // fork: convert_we runs in parallel with convert_x -> gate
    cudaEventRecord(ev_fork, 0);
    cudaStreamWaitEvent(s_we, ev_fork, 0);
    convert_we_kernel<<<4096, 256, 0, s_we>>>(We);
    cudaEventRecord(ev_join, s_we);

    convert_x_kernel<<<4096, 256>>>(x);
    gate_kernel<<<T_TOKENS / 32, 256>>>(x, Wg);

    // join: GEMM needs g_we + routing
    cudaStreamWaitEvent(0, ev_join, 0);
    dim3 grid(O_DIM / 128, ROWS_CAP / 128, 1);
    expert_gemm_hmma<<<grid, 256, GEMM_SMEM>>>();
    combine_kernel<<<T_TOKENS, 256>>>(be, out);
}